// round 17
// baseline (speedup 1.0000x reference)
#include <cuda_runtime.h>
#include <cuda_fp16.h>
#include <cstdint>

namespace {

constexpr int B = 2, N = 4096, D = 256, R = 64;
constexpr int TM = 64;         // n-rows per block
constexpr int TN = 64;         // m-tile
constexpr int THREADS = 512;   // 16 warps

// ---- prop smem layout in uint32 units; stride 36 (mod 32 == 4).
constexpr int STR = 36;
constexpr int OFE0  = 0;                     // 64 x 36, E double-buffered
constexpr int OFE1  = OFE0 + 64 * STR;
constexpr int OFK0  = OFE1 + 64 * STR;       // 64 x 36
constexpr int OFK1  = OFK0 + 64 * STR;
constexpr int OFV0  = OFK1 + 64 * STR;       // 256 x 36
constexpr int OFV1  = OFV0 + 256 * STR;
constexpr int OFST0 = OFV1 + 256 * STR;      // 64 (floats)
constexpr int OFST1 = OFST0 + 64;
constexpr int OFRD  = OFST1 + 64;            // 512 (floats)
constexpr int SMEM_U32 = OFRD + 512;
constexpr int SMEM_BYTES = SMEM_U32 * 4;     // ~110.5 KB

// ---- prep smem layout (floats)
constexpr int PVS  = 0;                      // 64 rows x 260 (val, fp32)
constexpr int PWQ  = PVS + 64 * 260;         // 128 x 64
constexpr int PWK  = PWQ + 128 * 64;         // 128 x 64
constexpr int PREP_FLOATS = PWK + 128 * 64;
constexpr int PREP_SMEM = PREP_FLOATS * 4;   // 132096 B

// fp16 pair-packed globals, NATURAL pair order (uint32 = half2)
__device__ uint32_t g_q[B * N * (R / 2)];
__device__ uint32_t g_k[B * N * (R / 2)];
__device__ uint32_t g_vt[B * D * (N / 2)];   // [b][d][m-pair]

typedef unsigned long long ull;

__device__ __forceinline__ uint32_t pack_h2(float lo, float hi) {
    __half2 h = __floats2half2_rn(lo, hi);
    return *reinterpret_cast<uint32_t*>(&h);
}
__device__ __forceinline__ ull bcast2(float v) {
    ull r;
    asm("mov.b64 %0, {%1, %1};" : "=l"(r) : "f"(v));
    return r;
}
__device__ __forceinline__ void unpack2(ull v, float& lo, float& hi) {
    asm("mov.b64 {%0, %1}, %2;" : "=f"(lo), "=f"(hi) : "l"(v));
}
__device__ __forceinline__ void fma2(ull& d, ull a, ull b) {
    asm("fma.rn.f32x2 %0, %1, %2, %0;" : "+l"(d) : "l"(a), "l"(b));
}
__device__ __forceinline__ uint32_t smem_u32p(const void* p) {
    uint32_t a;
    asm("{ .reg .u64 t; cvta.to.shared.u64 t, %1; cvt.u32.u64 %0, t; }" : "=r"(a) : "l"(p));
    return a;
}
__device__ __forceinline__ void cp16(uint32_t dst, const void* src) {
    asm volatile("cp.async.cg.shared.global [%0], [%1], 16;" :: "r"(dst), "l"(src));
}
__device__ __forceinline__ void cp_commit() { asm volatile("cp.async.commit_group;"); }
__device__ __forceinline__ void cp_wait0()  { asm volatile("cp.async.wait_group 0;"); }
__device__ __forceinline__ void cp_wait1()  { asm volatile("cp.async.wait_group 1;"); }

__device__ __forceinline__ void ldsm2(uint32_t& r0, uint32_t& r1, uint32_t addr) {
    asm volatile("ldmatrix.sync.aligned.m8n8.x2.shared.b16 {%0,%1}, [%2];"
                 : "=r"(r0), "=r"(r1) : "r"(addr));
}
__device__ __forceinline__ void ldsm4(uint32_t& r0, uint32_t& r1, uint32_t& r2,
                                      uint32_t& r3, uint32_t addr) {
    asm volatile("ldmatrix.sync.aligned.m8n8.x4.shared.b16 {%0,%1,%2,%3}, [%4];"
                 : "=r"(r0), "=r"(r1), "=r"(r2), "=r"(r3) : "r"(addr));
}
__device__ __forceinline__ void mma_f16(float (&d)[4], const uint32_t (&a)[4],
                                        uint32_t b0, uint32_t b1) {
    asm volatile(
        "mma.sync.aligned.m16n8k16.row.col.f32.f16.f16.f32 "
        "{%0,%1,%2,%3}, {%4,%5,%6,%7}, {%8,%9}, {%0,%1,%2,%3};"
        : "+f"(d[0]), "+f"(d[1]), "+f"(d[2]), "+f"(d[3])
        : "r"(a[0]), "r"(a[1]), "r"(a[2]), "r"(a[3]), "r"(b0), "r"(b1));
}

// ---------------------------------------------------------------------------
// Prep kernel (R16 verbatim).
// ---------------------------------------------------------------------------
__global__ void __launch_bounds__(THREADS) prep_kernel(const float* __restrict__ val,
                                                       const float* __restrict__ Wq,
                                                       const float* __restrict__ Wk) {
    extern __shared__ float ps[];
    const uint32_t sbase = smem_u32p(ps);

    const int b  = blockIdx.y;
    const int n0 = blockIdx.x * TM;
    const int t  = threadIdx.x;

    {
        const float* srcv = val + ((size_t)b * N + n0) * D;
#pragma unroll
        for (int it = 0; it < 8; ++it) {
            int p = t + it * THREADS;
            int row = p >> 6, c4 = p & 63;
            cp16(sbase + (uint32_t)(PVS + row * 260 + 4 * c4) * 4u, srcv + 4 * p);
        }
        cp_commit();
    }
    {
#pragma unroll
        for (int it = 0; it < 4; ++it) {
            int p = t + it * THREADS;
            cp16(sbase + (uint32_t)(PWQ + 4 * p) * 4u, Wq + 4 * p);
        }
#pragma unroll
        for (int it = 0; it < 4; ++it) {
            int p = t + it * THREADS;
            cp16(sbase + (uint32_t)(PWK + 4 * p) * 4u, Wk + 4 * p);
        }
        cp_commit();
    }
    cp_wait0();
    __syncthreads();

    const int cpair = t & 31;
    const int rg = t >> 5;

    ull aq[4], ak[4];
#pragma unroll
    for (int j = 0; j < 4; ++j) { aq[j] = 0ull; ak[j] = 0ull; }

#pragma unroll 1
    for (int c = 0; c < 2; ++c) {
        if (c == 1) {
            __syncthreads();
#pragma unroll
            for (int it = 0; it < 4; ++it) {
                int p = t + it * THREADS;
                cp16(sbase + (uint32_t)(PWQ + 4 * p) * 4u, Wq + 128 * 64 + 4 * p);
            }
#pragma unroll
            for (int it = 0; it < 4; ++it) {
                int p = t + it * THREADS;
                cp16(sbase + (uint32_t)(PWK + 4 * p) * 4u, Wk + 128 * 64 + 4 * p);
            }
            cp_commit();
            cp_wait0();
            __syncthreads();
        }
        const int gd0 = c * 128;
#pragma unroll 4
        for (int d = 0; d < 128; ++d) {
            ull wq2 = *reinterpret_cast<const ull*>(&ps[PWQ + d * 64 + 2 * cpair]);
            ull wk2 = *reinterpret_cast<const ull*>(&ps[PWK + d * 64 + 2 * cpair]);
#pragma unroll
            for (int j = 0; j < 4; ++j) {
                ull vb = bcast2(ps[PVS + (rg * 4 + j) * 260 + gd0 + d]);
                fma2(aq[j], vb, wq2);
                fma2(ak[j], vb, wk2);
            }
        }
    }

#pragma unroll
    for (int j = 0; j < 4; ++j) {
        const size_t base = ((size_t)b * N + n0 + rg * 4 + j) * 32;
        float lo, hi;
        unpack2(aq[j], lo, hi);
        g_q[base + cpair] = pack_h2(lo, hi);
        unpack2(ak[j], lo, hi);
        g_k[base + cpair] = pack_h2(lo, hi);
    }

    {
        uint32_t* gvt_b = g_vt + (size_t)b * D * (N / 2);
#pragma unroll
        for (int it = 0; it < 8; ++it) {
            int p = t + it * THREADS;
            int drow = p >> 4, j = p & 15;
            uint2 o;
            o.x = pack_h2(ps[PVS + (4 * j + 0) * 260 + drow],
                          ps[PVS + (4 * j + 1) * 260 + drow]);
            o.y = pack_h2(ps[PVS + (4 * j + 2) * 260 + drow],
                          ps[PVS + (4 * j + 3) * 260 + drow]);
            *reinterpret_cast<uint2*>(
                &gvt_b[(size_t)drow * (N / 2) + n0 / 2 + 2 * j]) = o;
        }
    }
}

// ---------------------------------------------------------------------------
// Prop kernel: R16 tiles (32x8 MMA1, 32x32 MMA2, ldmatrix) + single-barrier
// software pipeline: iteration i runs MMA1(i+1) and MMA2(i). E double-buffered;
// K/state prefetched one tile deeper than VT.
// ---------------------------------------------------------------------------
__global__ void __launch_bounds__(THREADS) prop_kernel(const float* __restrict__ state,
                                                       float* __restrict__ out_ds,
                                                       float* __restrict__ out_dv) {
    extern __shared__ float smf[];
    uint32_t* sm = reinterpret_cast<uint32_t*>(smf);
    const uint32_t sbase = smem_u32p(smf);

    const int b  = blockIdx.y;
    const int n0 = blockIdx.x * TM;
    const int t  = threadIdx.x;
    const int wid = t >> 5, lane = t & 31;
    const int g = lane >> 2, tg = lane & 3;
    const int wr = wid & 1;          // 32-row group
    const int wc = wid >> 1;         // 0..7

    const uint32_t* gk_b  = g_k + (size_t)b * N * 32;
    const uint32_t* gvt_b = g_vt + (size_t)b * D * (N / 2);
    const float* st_b = state + (size_t)b * N;

    auto prefetchK = [&](int m0, int buf) {
        const int ofk = buf ? OFK1 : OFK0;
        int row = t >> 3, cc = t & 7;
        cp16(sbase + (uint32_t)(ofk + row * STR + 4 * cc) * 4u,
             gk_b + (size_t)(m0 + row) * 32 + 4 * cc);
    };
    auto prefetchV = [&](int m0, int buf) {
        const int ofv = buf ? OFV1 : OFV0;
#pragma unroll
        for (int it = 0; it < 4; ++it) {
            int p = t + it * THREADS;
            int row = p >> 3, cc = p & 7;
            cp16(sbase + (uint32_t)(ofv + row * STR + 4 * cc) * 4u,
                 gvt_b + (size_t)row * (N / 2) + m0 / 2 + 4 * cc);
        }
    };
    auto prefetchST = [&](int m0, int buf) {
        const int ofst = buf ? OFST1 : OFST0;
        if (t < 16)
            cp16(sbase + (uint32_t)(ofst + 4 * t) * 4u, st_b + m0 + 4 * t);
    };

    // prologue: group0 = {K0, st0}; group1 = {K1, VT0, st1}
    prefetchK(0, 0); prefetchST(0, 0); cp_commit();
    prefetchK(TN, 1); prefetchV(0, 0); prefetchST(TN, 1); cp_commit();

    // ---- Q A-fragments (2 rowsets x 4 k16-steps)
    uint32_t aq[2][4][4];
#pragma unroll
    for (int s = 0; s < 2; ++s) {
        const uint32_t* q0 = g_q + ((size_t)b * N + n0 + 32 * wr + 16 * s + g) * 32;
        const uint32_t* q1 = q0 + 8 * 32;
#pragma unroll
        for (int ks = 0; ks < 4; ++ks) {
            aq[s][ks][0] = q0[8 * ks + tg];
            aq[s][ks][1] = q1[8 * ks + tg];
            aq[s][ks][2] = q0[8 * ks + tg + 4];
            aq[s][ks][3] = q1[8 * ks + tg + 4];
        }
    }

    // ldmatrix address components
    const int lrow = lane & 7;
    const int b1row = 8 * wc + lrow;                         // MMA1 B (K), x2
    const int b1kb  = (lane >> 3) & 1;
    const int earow0 = 32 * wr + 8 * ((lane >> 3) & 1) + lrow;   // MMA2 A (E), x4
    const int eakb   = lane >> 4;
    const int b2row0 = 32 * wc + 8 * (lane >> 4) + lrow;     // MMA2 B (VT), x4
    const int b2kb   = (lane >> 3) & 1;

    float dv[2][4][4];
#pragma unroll
    for (int s = 0; s < 2; ++s)
#pragma unroll
        for (int nt = 0; nt < 4; ++nt)
#pragma unroll
            for (int j = 0; j < 4; ++j) dv[s][nt][j] = 0.f;
    float ds[2][2] = {{0.f, 0.f}, {0.f, 0.f}};

    // MMA1(tile) + softsign + E-store into buffer (tile&1); accumulates ds.
    auto mma1_soft = [&](int tilebuf) {
        const int ofk  = tilebuf ? OFK1 : OFK0;
        const int ofst = tilebuf ? OFST1 : OFST0;
        const int ofe  = tilebuf ? OFE1 : OFE0;

        float sacc[2][4];
#pragma unroll
        for (int s = 0; s < 2; ++s)
#pragma unroll
            for (int j = 0; j < 4; ++j) sacc[s][j] = 0.f;

#pragma unroll
        for (int ks = 0; ks < 4; ++ks) {
            uint32_t kb0, kb1;
            ldsm2(kb0, kb1,
                  sbase + (uint32_t)(ofk + b1row * STR + 8 * ks + 4 * b1kb) * 4u);
            mma_f16(sacc[0], aq[0][ks], kb0, kb1);
            mma_f16(sacc[1], aq[1][ks], kb0, kb1);
        }

#pragma unroll
        for (int s = 0; s < 2; ++s) {
            const int c0 = 8 * wc + 2 * tg;
            float e00 = __fdividef(sacc[s][0], 1.f + fabsf(sacc[s][0]));
            float e01 = __fdividef(sacc[s][1], 1.f + fabsf(sacc[s][1]));
            float e10 = __fdividef(sacc[s][2], 1.f + fabsf(sacc[s][2]));
            float e11 = __fdividef(sacc[s][3], 1.f + fabsf(sacc[s][3]));
            float s0 = smf[ofst + c0], s1 = smf[ofst + c0 + 1];
            ds[s][0] = fmaf(e00, s0, fmaf(e01, s1, ds[s][0]));
            ds[s][1] = fmaf(e10, s0, fmaf(e11, s1, ds[s][1]));
            const int es = 4 * wc + tg;
            const int er = 32 * wr + 16 * s + g;
            sm[ofe + er * STR + es]       = pack_h2(e00, e01);
            sm[ofe + (er + 8) * STR + es] = pack_h2(e10, e11);
        }
    };

    auto mma2 = [&](int tilebuf) {
        const int ofe = tilebuf ? OFE1 : OFE0;
        const int ofv = tilebuf ? OFV1 : OFV0;
#pragma unroll
        for (int ks = 0; ks < 4; ++ks) {
            uint32_t a0[4], a1[4];
            ldsm4(a0[0], a0[1], a0[2], a0[3],
                  sbase + (uint32_t)(ofe + earow0 * STR + 8 * ks + 4 * eakb) * 4u);
            ldsm4(a1[0], a1[1], a1[2], a1[3],
                  sbase + (uint32_t)(ofe + (earow0 + 16) * STR + 8 * ks + 4 * eakb) * 4u);
#pragma unroll
            for (int u = 0; u < 2; ++u) {
                uint32_t v0, v1, v2, v3;
                ldsm4(v0, v1, v2, v3,
                      sbase + (uint32_t)(ofv + (b2row0 + 16 * u) * STR
                                         + 8 * ks + 4 * b2kb) * 4u);
                mma_f16(dv[0][2 * u],     a0, v0, v1);
                mma_f16(dv[0][2 * u + 1], a0, v2, v3);
                mma_f16(dv[1][2 * u],     a1, v0, v1);
                mma_f16(dv[1][2 * u + 1], a1, v2, v3);
            }
        }
    };

    // prologue compute: MMA1(0) needs only group0 (K0, st0)
    cp_wait1();
    __syncthreads();
    mma1_soft(0);

#pragma unroll 1
    for (int i = 0; i < N / TN; ++i) {
        cp_wait0();
        __syncthreads();   // K(i+1), VT(i), st(i+1) resident; E(i) visible

        if (i + 2 < N / TN) { prefetchK((i + 2) * TN, i & 1); prefetchST((i + 2) * TN, i & 1); }
        if (i + 1 < N / TN) { prefetchV((i + 1) * TN, (i + 1) & 1); }
        cp_commit();

        if (i + 1 < N / TN) mma1_soft((i + 1) & 1);
        mma2(i & 1);
    }

    // ---- epilogue: DV writes
#pragma unroll
    for (int s = 0; s < 2; ++s) {
        const int rowA = n0 + 32 * wr + 16 * s + g;
        float* dA = out_dv + ((size_t)b * N + rowA) * D;
        float* dB = dA + 8 * D;
#pragma unroll
        for (int nt = 0; nt < 4; ++nt) {
            const int col = 32 * wc + 8 * nt + 2 * tg;
            *reinterpret_cast<float2*>(dA + col) = make_float2(dv[s][nt][0], dv[s][nt][1]);
            *reinterpret_cast<float2*>(dB + col) = make_float2(dv[s][nt][2], dv[s][nt][3]);
        }
    }

    // ---- delta_state reduction
#pragma unroll
    for (int s = 0; s < 2; ++s)
#pragma unroll
        for (int h = 0; h < 2; ++h) {
            ds[s][h] += __shfl_xor_sync(0xFFFFFFFF, ds[s][h], 1);
            ds[s][h] += __shfl_xor_sync(0xFFFFFFFF, ds[s][h], 2);
        }
    __syncthreads();
    if (tg == 0) {
#pragma unroll
        for (int s = 0; s < 2; ++s) {
            smf[OFRD + (32 * wr + 16 * s + g) * 8 + wc]     = ds[s][0];
            smf[OFRD + (32 * wr + 16 * s + g + 8) * 8 + wc] = ds[s][1];
        }
    }
    __syncthreads();
    if (t < TM) {
        float r = 0.f;
#pragma unroll
        for (int j = 0; j < 8; ++j) r += smf[OFRD + t * 8 + j];
        out_ds[b * N + n0 + t] = r;
    }
}

}  // namespace

extern "C" void kernel_launch(void* const* d_in, const int* in_sizes, int n_in,
                              void* d_out, int out_size) {
    const float* state = (const float*)d_in[0];   // [B, N]
    const float* val   = (const float*)d_in[1];   // [B, N, D]
    const float* Wq    = (const float*)d_in[2];   // [D, R]
    const float* Wk    = (const float*)d_in[3];   // [D, R]

    float* out_ds = (float*)d_out;                // [B, N]
    float* out_dv = out_ds + B * N;               // [B, N, D]

    cudaFuncSetAttribute(prep_kernel, cudaFuncAttributeMaxDynamicSharedMemorySize, PREP_SMEM);
    cudaFuncSetAttribute(prop_kernel, cudaFuncAttributeMaxDynamicSharedMemorySize, SMEM_BYTES);

    prep_kernel<<<dim3(N / TM, B), THREADS, PREP_SMEM>>>(val, Wq, Wk);
    prop_kernel<<<dim3(N / TM, B), THREADS, SMEM_BYTES>>>(state, out_ds, out_dv);
}